// round 5
// baseline (speedup 1.0000x reference)
#include <cuda_runtime.h>
#include <math.h>

#define EPS 1e-5f

// ---------------- static scratch ----------------
__device__ float g_part[4*128*64*64];     // conv_down ci-split partials
__device__ float g_t2[2*128*64*64];
__device__ float g_g2[2*128*128*128];
__device__ float g_K1[2*9*128*128];
__device__ float g_Kp[2*4*9*128*128];     // pac K1 channel-split partials
__device__ float g_M1[2*9*64*64*64];
__device__ float g_y1[2*64*128*128];
__device__ float g_g1[2*64*256*256];
__device__ float g_K2[2*9*256*256];
__device__ float g_M2[2*9*32*128*128];
__device__ float g_y2[2*32*256*256];
__device__ float g_mean[1024];
__device__ float g_var[1024];
__device__ float g_na[1024];
__device__ float g_nc[1024];

// ---------------- instance stats ----------------
__global__ void stats_kernel(const float* __restrict__ x, int HW,
                             float* __restrict__ mean, float* __restrict__ var) {
    int bc = blockIdx.x;
    const float* p = x + (size_t)bc * HW;
    float s = 0.f, ss = 0.f;
    for (int i = threadIdx.x; i < HW; i += blockDim.x) {
        float v = p[i]; s += v; ss += v * v;
    }
    __shared__ float sh0[32], sh1[32];
    for (int o = 16; o; o >>= 1) {
        s  += __shfl_down_sync(0xffffffffu, s, o);
        ss += __shfl_down_sync(0xffffffffu, ss, o);
    }
    int wid = threadIdx.x >> 5, lid = threadIdx.x & 31;
    if (lid == 0) { sh0[wid] = s; sh1[wid] = ss; }
    __syncthreads();
    if (wid == 0) {
        int nw = blockDim.x >> 5;
        s  = (lid < nw) ? sh0[lid] : 0.f;
        ss = (lid < nw) ? sh1[lid] : 0.f;
        for (int o = 16; o; o >>= 1) {
            s  += __shfl_down_sync(0xffffffffu, s, o);
            ss += __shfl_down_sync(0xffffffffu, ss, o);
        }
        if (lid == 0) {
            float m = s / (float)HW;
            mean[bc] = m;
            var[bc]  = ss / (float)HW - m * m;
        }
    }
}

__global__ void inorm_coef(const float* __restrict__ mean, const float* __restrict__ var,
                           float* __restrict__ a, float* __restrict__ c, int n) {
    int i = blockIdx.x * blockDim.x + threadIdx.x;
    if (i < n) {
        float r = rsqrtf(var[i] + EPS);
        a[i] = r; c[i] = -mean[i] * r;
    }
}

__global__ void dinorm_coef(const float* __restrict__ mean, const float* __restrict__ var,
                            float* __restrict__ a, float* __restrict__ c, int n) {
    int i = blockIdx.x * blockDim.x + threadIdx.x;
    if (i < n) {
        float m = mean[i], v = var[i];
        float r1 = rsqrtf(v + EPS);
        float a1 = 1.f + r1, c1 = -m * r1;
        float m2 = a1 * m + c1;
        float v2 = a1 * a1 * v;
        float r2 = rsqrtf(v2 + EPS);
        a[i] = a1 * (1.f + r2);
        c[i] = c1 * (1.f + r2) - m2 * r2;
    }
}

// ---------------- register-tiled 3x3 conv v4: CT-channel staged smem ----------------
// block (16,8)=128 thr; tile 32 wide x (8*PXH) tall; thread: 2 cols x PXH rows.
// CT input channels staged per barrier pair.
template<int CO_BLK, int PXH, int CT, int CI_SPLIT, bool BIAS>
__global__ void __launch_bounds__(128) conv3x3_v4(
        const float* __restrict__ in, const float* __restrict__ w,
        const float* __restrict__ bias, float* __restrict__ out,
        int Ci, int Co, int Hs, int Ws,
        const float* __restrict__ na, const float* __restrict__ nc) {
    const int TW = 32, TH = 8 * PXH;
    const int ROWS = TH + 2, COLS = TW + 2, STR = TW + 4;
    int tiles_x = Ws / TW;
    int tx0 = (blockIdx.x % tiles_x) * TW;
    int ty0 = (blockIdx.x / tiles_x) * TH;
    int co0 = blockIdx.y * CO_BLK;
    int zz = blockIdx.z;
    int b = zz / CI_SPLIT;
    int gsp = zz % CI_SPLIT;
    int ciN = Ci / CI_SPLIT;
    int ci0 = gsp * ciN;
    int lx = threadIdx.x, ly = threadIdx.y;
    int tid = ly * 16 + lx;

    __shared__ float xs[CT][ROWS][STR];
    __shared__ float ws_s[CT][CO_BLK][9];

    float acc[CO_BLK][PXH][2];
    #pragma unroll
    for (int u = 0; u < CO_BLK; u++)
        #pragma unroll
        for (int r = 0; r < PXH; r++) { acc[u][r][0] = 0.f; acc[u][r][1] = 0.f; }

    const float* inb = in + ((size_t)b * Ci + ci0) * Hs * Ws;
    for (int cc0 = 0; cc0 < ciN; cc0 += CT) {
        // stage CT channels of input tile
        #pragma unroll
        for (int t = 0; t < CT; t++) {
            int ci = ci0 + cc0 + t;
            const float* inc = inb + (size_t)(cc0 + t) * Hs * Ws;
            float aa = 1.f, ccv = 0.f;
            if (na) { aa = na[b * Ci + ci]; ccv = nc[b * Ci + ci]; }
            #pragma unroll
            for (int i = tid; i < ROWS * COLS; i += 128) {
                int r = i / COLS, c = i % COLS;
                int gy = ty0 + r - 1, gx = tx0 + c - 1;
                float v = 0.f;
                if ((unsigned)gy < (unsigned)Hs && (unsigned)gx < (unsigned)Ws)
                    v = fmaf(aa, inc[gy * Ws + gx], ccv);
                xs[t][r][c] = v;
            }
        }
        // stage weights for CT channels
        for (int i = tid; i < CT * CO_BLK * 9; i += 128) {
            int t = i / (CO_BLK * 9);
            int rem = i - t * CO_BLK * 9;
            int u = rem / 9, tap = rem - u * 9;
            ws_s[t][u][tap] = w[((size_t)(co0 + u) * Ci + ci0 + cc0 + t) * 9 + tap];
        }
        __syncthreads();

        #pragma unroll
        for (int t = 0; t < CT; t++) {
            float xr[PXH + 2][4];
            #pragma unroll
            for (int r = 0; r < PXH + 2; r++)
                #pragma unroll
                for (int c = 0; c < 4; c++)
                    xr[r][c] = xs[t][ly * PXH + r][2 * lx + c];

            #pragma unroll
            for (int u = 0; u < CO_BLK; u++) {
                #pragma unroll
                for (int i = 0; i < 3; i++)
                    #pragma unroll
                    for (int j = 0; j < 3; j++) {
                        float wv = ws_s[t][u][i * 3 + j];
                        #pragma unroll
                        for (int r = 0; r < PXH; r++) {
                            acc[u][r][0] = fmaf(xr[i + r][j],     wv, acc[u][r][0]);
                            acc[u][r][1] = fmaf(xr[i + r][j + 1], wv, acc[u][r][1]);
                        }
                    }
            }
        }
        __syncthreads();
    }

    int oy = ty0 + ly * PXH, ox = tx0 + 2 * lx;
    #pragma unroll
    for (int u = 0; u < CO_BLK; u++) {
        float bv = BIAS ? bias[co0 + u] : 0.f;
        #pragma unroll
        for (int r = 0; r < PXH; r++) {
            float* op = out + (((size_t)zz * Co + co0 + u) * Hs + oy + r) * Ws + ox;
            *(float2*)op = make_float2(acc[u][r][0] + bv, acc[u][r][1] + bv);
        }
    }
}

// ---------------- fused: x = p0+p1+b_down; out = W_mid*x + b_mid + x ----------------
// grid (HW4/128, Co/8, B), block 128.
__global__ void __launch_bounds__(128) conv1x1_res4_fused(
        const float* __restrict__ part, const float* __restrict__ w,
        const float* __restrict__ bias_mid, const float* __restrict__ bias_down,
        float* __restrict__ out, int Cc, int HW4) {
    int p = blockIdx.x * 128 + threadIdx.x;
    int o0 = blockIdx.y * 8;
    int b = blockIdx.z;
    __shared__ float ws[8 * 128];
    for (int i = threadIdx.x; i < 8 * Cc; i += 128)
        ws[i] = w[(o0 + i / Cc) * Cc + i % Cc];
    __syncthreads();
    const float4* p0 = (const float4*)part + (size_t)(2 * b) * Cc * HW4;
    const float4* p1 = (const float4*)part + (size_t)(2 * b + 1) * Cc * HW4;
    float4 acc[8];
    #pragma unroll
    for (int u = 0; u < 8; u++) acc[u] = make_float4(0.f, 0.f, 0.f, 0.f);
    for (int ci = 0; ci < Cc; ci++) {
        float4 a = p0[(size_t)ci * HW4 + p];
        float4 bq = p1[(size_t)ci * HW4 + p];
        float bd = bias_down[ci];
        float4 xv = make_float4(a.x + bq.x + bd, a.y + bq.y + bd,
                                a.z + bq.z + bd, a.w + bq.w + bd);
        #pragma unroll
        for (int u = 0; u < 8; u++) {
            float wv = ws[u * Cc + ci];
            acc[u].x = fmaf(wv, xv.x, acc[u].x);
            acc[u].y = fmaf(wv, xv.y, acc[u].y);
            acc[u].z = fmaf(wv, xv.z, acc[u].z);
            acc[u].w = fmaf(wv, xv.w, acc[u].w);
        }
    }
    float4* ob = (float4*)out + (size_t)b * Cc * HW4;
    #pragma unroll
    for (int u = 0; u < 8; u++) {
        int ci = o0 + u;
        float4 a = p0[(size_t)ci * HW4 + p];
        float4 bq = p1[(size_t)ci * HW4 + p];
        float bd = bias_down[ci];
        float bv = bias_mid[ci];
        float4 o;
        o.x = acc[u].x + bv + a.x + bq.x + bd;
        o.y = acc[u].y + bv + a.y + bq.y + bd;
        o.z = acc[u].z + bv + a.z + bq.z + bd;
        o.w = acc[u].w + bv + a.w + bq.w + bd;
        ob[(size_t)ci * HW4 + p] = o;
    }
}

// ---------------- PAC gaussian kernel, channel-split ----------------
// grid (tiles, G, B). If G==1 writes exp(-0.5*acc) straight to Kout;
// else writes partial acc to Kpart[b][gr][9][HW].
__global__ void pac_K_part(const float* __restrict__ g, float* __restrict__ Kout,
                           float* __restrict__ Kpart, int Cg, int Hg, int Wg, int G) {
    int tiles_x = Wg / 16;
    int tx0 = (blockIdx.x % tiles_x) * 16, ty0 = (blockIdx.x / tiles_x) * 16;
    int gr = blockIdx.y, b = blockIdx.z;
    int cN = Cg / G, c0 = gr * cN;
    int lx = threadIdx.x, ly = threadIdx.y;
    int tid = ly * 16 + lx;
    __shared__ float gs[18][19];
    float acc[9];
    #pragma unroll
    for (int k = 0; k < 9; k++) acc[k] = 0.f;
    const float* gb = g + ((size_t)b * Cg + c0) * Hg * Wg;
    for (int c = 0; c < cN; c++) {
        const float* gc = gb + (size_t)c * Hg * Wg;
        #pragma unroll
        for (int i = tid; i < 18 * 18; i += 256) {
            int r = i / 18, cx = i % 18;
            int yy = ty0 + r - 1, xx = tx0 + cx - 1;
            gs[r][cx] = (yy >= 0 && yy < Hg && xx >= 0 && xx < Wg) ? gc[yy * Wg + xx] : 0.f;
        }
        __syncthreads();
        float ctr = gs[ly + 1][lx + 1];
        #pragma unroll
        for (int i = 0; i < 3; i++)
            #pragma unroll
            for (int j = 0; j < 3; j++) {
                float d = gs[ly + i][lx + j] - ctr;
                acc[i * 3 + j] = fmaf(d, d, acc[i * 3 + j]);
            }
        __syncthreads();
    }
    size_t px = (size_t)(ty0 + ly) * Wg + tx0 + lx;
    if (G == 1) {
        size_t base = (size_t)b * 9 * Hg * Wg + px;
        #pragma unroll
        for (int k = 0; k < 9; k++)
            Kout[base + (size_t)k * Hg * Wg] = __expf(-0.5f * acc[k]);
    } else {
        size_t base = ((size_t)(b * G + gr) * 9) * Hg * Wg + px;
        #pragma unroll
        for (int k = 0; k < 9; k++)
            Kpart[base + (size_t)k * Hg * Wg] = acc[k];
    }
}

// K[b][k][px] = exp(-0.5 * sum_gr Kpart[b][gr][k][px]); N = B*9*HW
__global__ void pac_K_comb(const float* __restrict__ Kpart, float* __restrict__ K,
                           int G, int planes9HW, int N) {
    int i = blockIdx.x * 256 + threadIdx.x;
    if (i >= N) return;
    int b = i / planes9HW;
    int rem = i - b * planes9HW;
    float s = 0.f;
    const float* p = Kpart + (size_t)b * G * planes9HW + rem;
    for (int gr = 0; gr < G; gr++) s += p[(size_t)gr * planes9HW];
    K[i] = __expf(-0.5f * s);
}

// ---------------- tap GEMM ----------------
__global__ void __launch_bounds__(128) tap_gemm(
        const float* __restrict__ x, const float* __restrict__ w,
        float* __restrict__ M, int Cin, int Co, int HW4,
        const float* __restrict__ na, const float* __restrict__ nc) {
    int p = blockIdx.x * 256 + threadIdx.x;
    int kc0 = blockIdx.y * 8;
    int b = blockIdx.z;
    int k = kc0 / Co, co0 = kc0 % Co;
    __shared__ float ws[8 * 128];
    for (int i = threadIdx.x; i < 8 * Cin; i += 128) {
        int u = i / Cin, ci = i % Cin;
        ws[i] = w[((size_t)ci * Co + co0 + u) * 9 + k];
    }
    __syncthreads();
    const float4* xb = (const float4*)x + (size_t)b * Cin * HW4;
    float4 a0[8], a1[8];
    #pragma unroll
    for (int u = 0; u < 8; u++) { a0[u] = make_float4(0, 0, 0, 0); a1[u] = make_float4(0, 0, 0, 0); }
    for (int ci = 0; ci < Cin; ci++) {
        float4 x0 = xb[(size_t)ci * HW4 + p];
        float4 x1 = xb[(size_t)ci * HW4 + p + 128];
        if (na) {
            float aa = na[b * Cin + ci], cc = nc[b * Cin + ci];
            x0.x = fmaf(aa, x0.x, cc); x0.y = fmaf(aa, x0.y, cc);
            x0.z = fmaf(aa, x0.z, cc); x0.w = fmaf(aa, x0.w, cc);
            x1.x = fmaf(aa, x1.x, cc); x1.y = fmaf(aa, x1.y, cc);
            x1.z = fmaf(aa, x1.z, cc); x1.w = fmaf(aa, x1.w, cc);
        }
        #pragma unroll
        for (int u = 0; u < 8; u++) {
            float wv = ws[u * Cin + ci];
            a0[u].x = fmaf(wv, x0.x, a0[u].x); a0[u].y = fmaf(wv, x0.y, a0[u].y);
            a0[u].z = fmaf(wv, x0.z, a0[u].z); a0[u].w = fmaf(wv, x0.w, a0[u].w);
            a1[u].x = fmaf(wv, x1.x, a1[u].x); a1[u].y = fmaf(wv, x1.y, a1[u].y);
            a1[u].z = fmaf(wv, x1.z, a1[u].z); a1[u].w = fmaf(wv, x1.w, a1[u].w);
        }
    }
    float4* Mb = (float4*)M + (size_t)b * 9 * Co * HW4;
    #pragma unroll
    for (int u = 0; u < 8; u++) {
        Mb[(size_t)(kc0 + u) * HW4 + p] = a0[u];
        Mb[(size_t)(kc0 + u) * HW4 + p + 128] = a1[u];
    }
}

// ---------------- PAC combine ----------------
template<int CO_T>
__global__ void pac_combine(const float* __restrict__ M, const float* __restrict__ K,
                            const float* __restrict__ bias, float* __restrict__ out,
                            int Co, int Hs, int Ws) {
    int Ho = 2 * Hs, Wo = 2 * Ws;
    int px = blockIdx.x * 256 + threadIdx.x;
    int h = px / Wo, w = px % Wo;
    int co0 = blockIdx.y * CO_T;
    int b = blockIdx.z;

    float acc[CO_T];
    #pragma unroll
    for (int u = 0; u < CO_T; u++) acc[u] = bias[co0 + u];

    int nr, ry[2], rk[2];
    if (h & 1) {
        nr = 2; rk[0] = 0; ry[0] = (h - 1) >> 1; rk[1] = 2; ry[1] = (h + 1) >> 1;
        if (ry[1] >= Hs) nr = 1;
    } else { nr = 1; rk[0] = 1; ry[0] = h >> 1; }
    int ncn, cx[2], ck[2];
    if (w & 1) {
        ncn = 2; ck[0] = 0; cx[0] = (w - 1) >> 1; ck[1] = 2; cx[1] = (w + 1) >> 1;
        if (cx[1] >= Ws) ncn = 1;
    } else { ncn = 1; ck[0] = 1; cx[0] = w >> 1; }

    const float* Kb = K + (size_t)b * 9 * Ho * Wo + px;
    const float* Mb = M + (size_t)b * 9 * Co * Hs * Ws;
    int HsWs = Hs * Ws;
    for (int rr = 0; rr < nr; rr++)
        for (int cc = 0; cc < ncn; cc++) {
            int k = rk[rr] * 3 + ck[cc];
            float Kv = __ldg(Kb + (size_t)k * Ho * Wo);
            const float* Mp = Mb + ((size_t)k * Co + co0) * HsWs + ry[rr] * Ws + cx[cc];
            #pragma unroll
            for (int u = 0; u < CO_T; u++)
                acc[u] = fmaf(Kv, __ldg(Mp + (size_t)u * HsWs), acc[u]);
        }
    #pragma unroll
    for (int u = 0; u < CO_T; u++)
        out[(((size_t)b * Co + co0 + u) * Ho + h) * Wo + w] = acc[u];
}

// ---------------- driver ----------------
extern "C" void kernel_launch(void* const* d_in, const int* in_sizes, int n_in,
                              void* d_out, int out_size) {
    const float* x      = (const float*)d_in[0];
    const float* ef2    = (const float*)d_in[1];
    const float* ef1    = (const float*)d_in[2];
    const float* W_down = (const float*)d_in[3];
    const float* b_down = (const float*)d_in[4];
    const float* W_mid  = (const float*)d_in[5];
    const float* b_mid  = (const float*)d_in[6];
    const float* W_adj2 = (const float*)d_in[7];
    const float* b_adj2 = (const float*)d_in[8];
    const float* W_adj1 = (const float*)d_in[9];
    const float* b_adj1 = (const float*)d_in[10];
    const float* W16    = (const float*)d_in[11];
    const float* b16    = (const float*)d_in[12];
    const float* W20    = (const float*)d_in[13];
    const float* b20    = (const float*)d_in[14];
    const float* W24    = (const float*)d_in[15];
    const float* b24    = (const float*)d_in[16];
    float* out = (float*)d_out;

    float *part, *t2, *g2, *K1, *Kp, *M1, *y1, *g1, *K2, *M2, *y2, *mean, *var, *na, *nc;
    cudaGetSymbolAddress((void**)&part, g_part);
    cudaGetSymbolAddress((void**)&t2, g_t2);
    cudaGetSymbolAddress((void**)&g2, g_g2);
    cudaGetSymbolAddress((void**)&K1, g_K1);
    cudaGetSymbolAddress((void**)&Kp, g_Kp);
    cudaGetSymbolAddress((void**)&M1, g_M1);
    cudaGetSymbolAddress((void**)&y1, g_y1);
    cudaGetSymbolAddress((void**)&g1, g_g1);
    cudaGetSymbolAddress((void**)&K2, g_K2);
    cudaGetSymbolAddress((void**)&M2, g_M2);
    cudaGetSymbolAddress((void**)&y2, g_y2);
    cudaGetSymbolAddress((void**)&mean, g_mean);
    cudaGetSymbolAddress((void**)&var, g_var);
    cudaGetSymbolAddress((void**)&na, g_na);
    cudaGetSymbolAddress((void**)&nc, g_nc);

    dim3 cblk(16, 8);
    dim3 blk16(16, 16);

    // 1) inorm(x) coefficients
    stats_kernel<<<512, 256>>>(x, 64 * 64, mean, var);
    inorm_coef<<<2, 256>>>(mean, var, na, nc, 512);

    // 2) conv_down 256->128 @64x64, norm fused, Ci split G=2 -> partials
    conv3x3_v4<8, 2, 4, 2, false><<<dim3(8, 16, 4), cblk>>>(x, W_down, b_down, part,
                                                            256, 128, 64, 64, na, nc);

    // 3) fused partial-reduce + 1x1 + residual
    conv1x1_res4_fused<<<dim3(8, 16, 2), 128>>>(part, W_mid, b_mid, b_down, t2, 128, 1024);

    // 4) g2 = adjust_ef_lv2: 64->128 @128x128
    conv3x3_v4<8, 4, 4, 1, true><<<dim3(16, 16, 2), cblk>>>(ef2, W_adj2, b_adj2, g2,
                                                            64, 128, 128, 128,
                                                            (const float*)0, (const float*)0);

    // 5) PAC kernel 1, channel split G=4 + combine
    pac_K_part<<<dim3(64, 4, 2), blk16>>>(g2, K1, Kp, 128, 128, 128, 4);
    pac_K_comb<<<1152, 256>>>(Kp, K1, 4, 9 * 128 * 128, 2 * 9 * 128 * 128);

    // 6) pacT1 = tap GEMM + combine: 128->64, 64x64 -> 128x128
    tap_gemm<<<dim3(4, 72, 2), 128>>>(t2, W16, M1, 128, 64, 1024,
                                      (const float*)0, (const float*)0);
    pac_combine<8><<<dim3(64, 8, 2), 256>>>(M1, K1, b16, y1, 64, 64, 64);

    // 7) dinorm coefs for y1 (affine fused into next tap_gemm)
    stats_kernel<<<128, 256>>>(y1, 128 * 128, mean, var);
    dinorm_coef<<<1, 256>>>(mean, var, na, nc, 128);

    // 8) g1 = adjust_ef_lv1: 32->64 @256x256
    conv3x3_v4<8, 4, 4, 1, true><<<dim3(64, 8, 2), cblk>>>(ef1, W_adj1, b_adj1, g1,
                                                           32, 64, 256, 256,
                                                           (const float*)0, (const float*)0);

    // 9) PAC kernel 2 (G=1, direct)
    pac_K_part<<<dim3(256, 1, 2), blk16>>>(g1, K2, Kp, 64, 256, 256, 1);

    // 10) pacT2 = tap GEMM (y1 affine fused) + combine: 64->32, 128x128 -> 256x256
    tap_gemm<<<dim3(16, 36, 2), 128>>>(y1, W20, M2, 64, 32, 4096, na, nc);
    pac_combine<8><<<dim3(256, 4, 2), 256>>>(M2, K2, b20, y2, 32, 128, 128);

    // 11) dinorm coefs for y2 (affine fused into final conv)
    stats_kernel<<<64, 256>>>(y2, 256 * 256, mean, var);
    dinorm_coef<<<1, 64>>>(mean, var, na, nc, 64);

    // 12) final conv 32->3 @256x256 (y2 affine fused)
    conv3x3_v4<3, 2, 4, 1, true><<<dim3(128, 1, 2), cblk>>>(y2, W24, b24, out,
                                                            32, 3, 256, 256, na, nc);
}

// round 7
// speedup vs baseline: 1.5183x; 1.5183x over previous
#include <cuda_runtime.h>
#include <math.h>

#define EPS 1e-5f

// ---------------- static scratch ----------------
__device__ float g_t1[2*128*64*64];
__device__ float g_part[4*128*64*64];
__device__ float g_t2[2*128*64*64];
__device__ float g_g2[2*128*128*128];
__device__ float g_K1[2*9*128*128];
__device__ float g_M1[2*9*64*64*64];
__device__ float g_y1[2*64*128*128];
__device__ float g_g1[2*64*256*256];
__device__ float g_K2[2*9*256*256];
__device__ float g_M2[2*9*32*128*128];
__device__ float g_y2[2*32*256*256];
__device__ float g_na[1024];
__device__ float g_nc[1024];

// ---------------- instance stats + fused coefficient ----------------
// DMODE 0: single inorm coefs (a = rsqrt(v+eps), c = -m*a)
// DMODE 1: double (inorm+residual) collapsed affine coefs
template<int DMODE>
__global__ void stats_coef(const float* __restrict__ x, int HW,
                           float* __restrict__ na, float* __restrict__ nc) {
    int bc = blockIdx.x;
    const float* p = x + (size_t)bc * HW;
    float s = 0.f, ss = 0.f;
    for (int i = threadIdx.x; i < HW; i += blockDim.x) {
        float v = p[i]; s += v; ss += v * v;
    }
    __shared__ float sh0[32], sh1[32];
    for (int o = 16; o; o >>= 1) {
        s  += __shfl_down_sync(0xffffffffu, s, o);
        ss += __shfl_down_sync(0xffffffffu, ss, o);
    }
    int wid = threadIdx.x >> 5, lid = threadIdx.x & 31;
    if (lid == 0) { sh0[wid] = s; sh1[wid] = ss; }
    __syncthreads();
    if (wid == 0) {
        int nw = blockDim.x >> 5;
        s  = (lid < nw) ? sh0[lid] : 0.f;
        ss = (lid < nw) ? sh1[lid] : 0.f;
        for (int o = 16; o; o >>= 1) {
            s  += __shfl_down_sync(0xffffffffu, s, o);
            ss += __shfl_down_sync(0xffffffffu, ss, o);
        }
        if (lid == 0) {
            float m = s / (float)HW;
            float v = ss / (float)HW - m * m;
            if (DMODE == 0) {
                float r = rsqrtf(v + EPS);
                na[bc] = r; nc[bc] = -m * r;
            } else {
                float r1 = rsqrtf(v + EPS);
                float a1 = 1.f + r1, c1 = -m * r1;
                float m2 = a1 * m + c1;
                float v2 = a1 * a1 * v;
                float r2 = rsqrtf(v2 + EPS);
                na[bc] = a1 * (1.f + r2);
                nc[bc] = c1 * (1.f + r2) - m2 * r2;
            }
        }
    }
}

// ---------------- register-tiled 3x3 conv: 16 co, 2x2 px/thread ----------------
// block (16,8)=128 thr; out tile 32x16; thread: 2 cols x PXH rows; CO_BLK co per block.
template<int CO_BLK, int PXH, int CI_SPLIT, bool BIAS>
__global__ void __launch_bounds__(128) conv3x3_v2(
        const float* __restrict__ in, const float* __restrict__ w,
        const float* __restrict__ bias, float* __restrict__ out,
        int Ci, int Co, int Hs, int Ws,
        const float* __restrict__ na, const float* __restrict__ nc) {
    const int TW = 32, TH = 8 * PXH;
    int tiles_x = Ws / TW;
    int tx0 = (blockIdx.x % tiles_x) * TW;
    int ty0 = (blockIdx.x / tiles_x) * TH;
    int co0 = blockIdx.y * CO_BLK;
    int zz = blockIdx.z;
    int b = zz / CI_SPLIT;
    int gsp = zz % CI_SPLIT;
    int ciN = Ci / CI_SPLIT;
    int ci0 = gsp * ciN;
    int lx = threadIdx.x, ly = threadIdx.y;
    int tid = ly * 16 + lx;

    __shared__ float xs[TH + 2][TW + 4];
    __shared__ float ws_s[CO_BLK][9];

    float acc[CO_BLK][PXH][2];
    #pragma unroll
    for (int u = 0; u < CO_BLK; u++)
        #pragma unroll
        for (int r = 0; r < PXH; r++) { acc[u][r][0] = 0.f; acc[u][r][1] = 0.f; }

    const float* inb = in + ((size_t)b * Ci + ci0) * Hs * Ws;
    for (int ci = 0; ci < ciN; ci++) {
        const float* inc = inb + (size_t)ci * Hs * Ws;
        float aa = 1.f, cc0 = 0.f;
        if (na) { aa = na[b * Ci + ci0 + ci]; cc0 = nc[b * Ci + ci0 + ci]; }
        #pragma unroll 4
        for (int i = tid; i < (TH + 2) * (TW + 2); i += 128) {
            int r = i / (TW + 2), c = i % (TW + 2);
            int gy = ty0 + r - 1, gx = tx0 + c - 1;
            float v = 0.f;
            if ((unsigned)gy < (unsigned)Hs && (unsigned)gx < (unsigned)Ws)
                v = fmaf(aa, inc[gy * Ws + gx], cc0);
            xs[r][c] = v;
        }
        #pragma unroll
        for (int i = tid; i < CO_BLK * 9; i += 128)
            ws_s[i / 9][i % 9] = w[((size_t)(co0 + i / 9) * Ci + ci0 + ci) * 9 + i % 9];
        __syncthreads();

        float xr[PXH + 2][4];
        #pragma unroll
        for (int r = 0; r < PXH + 2; r++)
            #pragma unroll
            for (int c = 0; c < 4; c++)
                xr[r][c] = xs[ly * PXH + r][2 * lx + c];

        #pragma unroll
        for (int u = 0; u < CO_BLK; u++) {
            #pragma unroll
            for (int i = 0; i < 3; i++)
                #pragma unroll
                for (int j = 0; j < 3; j++) {
                    float wv = ws_s[u][i * 3 + j];
                    #pragma unroll
                    for (int r = 0; r < PXH; r++) {
                        acc[u][r][0] = fmaf(xr[i + r][j],     wv, acc[u][r][0]);
                        acc[u][r][1] = fmaf(xr[i + r][j + 1], wv, acc[u][r][1]);
                    }
                }
        }
        __syncthreads();
    }

    int oy = ty0 + ly * PXH, ox = tx0 + 2 * lx;
    #pragma unroll
    for (int u = 0; u < CO_BLK; u++) {
        float bv = BIAS ? bias[co0 + u] : 0.f;
        #pragma unroll
        for (int r = 0; r < PXH; r++) {
            float* op = out + (((size_t)zz * Co + co0 + u) * Hs + oy + r) * Ws + ox;
            *(float2*)op = make_float2(acc[u][r][0] + bv, acc[u][r][1] + bv);
        }
    }
}

// reduce 2 ci-split partials + bias
__global__ void reduce2_bias(const float* __restrict__ p, const float* __restrict__ bias,
                             float* __restrict__ out, int Co, int HW, int N) {
    int i = blockIdx.x * 256 + threadIdx.x;
    if (i >= N) return;
    int b = i / (Co * HW);
    int rem = i - b * Co * HW;
    int co = rem / HW;
    out[i] = p[(size_t)(2 * b) * Co * HW + rem] + p[(size_t)(2 * b + 1) * Co * HW + rem] + bias[co];
}

// ---------------- 1x1 conv + residual, float4 ----------------
__global__ void conv1x1_res4(const float* __restrict__ x, const float* __restrict__ w,
                             const float* __restrict__ bias, float* __restrict__ out,
                             int Cc, int HW4) {
    int p = blockIdx.x * 128 + threadIdx.x;
    int o0 = blockIdx.y * 8;
    int b = blockIdx.z;
    __shared__ float ws[8 * 128];
    for (int i = threadIdx.x; i < 8 * Cc; i += 128)
        ws[i] = w[(o0 + i / Cc) * Cc + i % Cc];
    __syncthreads();
    const float4* xb = (const float4*)x + (size_t)b * Cc * HW4;
    float4 acc[8];
    #pragma unroll
    for (int u = 0; u < 8; u++) acc[u] = make_float4(0.f, 0.f, 0.f, 0.f);
    for (int ci = 0; ci < Cc; ci++) {
        float4 xv = xb[(size_t)ci * HW4 + p];
        #pragma unroll
        for (int u = 0; u < 8; u++) {
            float wv = ws[u * Cc + ci];
            acc[u].x = fmaf(wv, xv.x, acc[u].x);
            acc[u].y = fmaf(wv, xv.y, acc[u].y);
            acc[u].z = fmaf(wv, xv.z, acc[u].z);
            acc[u].w = fmaf(wv, xv.w, acc[u].w);
        }
    }
    float4* ob = (float4*)out + (size_t)b * Cc * HW4;
    #pragma unroll
    for (int u = 0; u < 8; u++) {
        float bv = bias[o0 + u];
        float4 rv = xb[(size_t)(o0 + u) * HW4 + p];
        float4 o;
        o.x = acc[u].x + bv + rv.x;
        o.y = acc[u].y + bv + rv.y;
        o.z = acc[u].z + bv + rv.z;
        o.w = acc[u].w + bv + rv.w;
        ob[(size_t)(o0 + u) * HW4 + p] = o;
    }
}

// ---------------- PAC gaussian kernel ----------------
__global__ void pac_kernel_K(const float* __restrict__ g, float* __restrict__ K,
                             int Cg, int Hg, int Wg) {
    int tiles_x = Wg / 16;
    int tx0 = (blockIdx.x % tiles_x) * 16, ty0 = (blockIdx.x / tiles_x) * 16;
    int b = blockIdx.y;
    int lx = threadIdx.x, ly = threadIdx.y;
    int tid = ly * 16 + lx;
    __shared__ float gs[18][19];
    float acc[9];
    #pragma unroll
    for (int k = 0; k < 9; k++) acc[k] = 0.f;
    const float* gb = g + (size_t)b * Cg * Hg * Wg;
    for (int c = 0; c < Cg; c++) {
        const float* gc = gb + (size_t)c * Hg * Wg;
        #pragma unroll
        for (int i = tid; i < 18 * 18; i += 256) {
            int r = i / 18, cx = i % 18;
            int yy = ty0 + r - 1, xx = tx0 + cx - 1;
            gs[r][cx] = (yy >= 0 && yy < Hg && xx >= 0 && xx < Wg) ? gc[yy * Wg + xx] : 0.f;
        }
        __syncthreads();
        float ctr = gs[ly + 1][lx + 1];
        #pragma unroll
        for (int i = 0; i < 3; i++)
            #pragma unroll
            for (int j = 0; j < 3; j++) {
                float d = gs[ly + i][lx + j] - ctr;
                acc[i * 3 + j] = fmaf(d, d, acc[i * 3 + j]);
            }
        __syncthreads();
    }
    size_t base = ((size_t)b * 9) * Hg * Wg + (size_t)(ty0 + ly) * Wg + tx0 + lx;
    #pragma unroll
    for (int k = 0; k < 9; k++)
        K[base + (size_t)k * Hg * Wg] = __expf(-0.5f * acc[k]);
}

// ---------------- tap GEMM ----------------
__global__ void __launch_bounds__(128) tap_gemm(
        const float* __restrict__ x, const float* __restrict__ w,
        float* __restrict__ M, int Cin, int Co, int HW4,
        const float* __restrict__ na, const float* __restrict__ nc) {
    int p = blockIdx.x * 256 + threadIdx.x;
    int kc0 = blockIdx.y * 8;
    int b = blockIdx.z;
    int k = kc0 / Co, co0 = kc0 % Co;
    __shared__ float ws[8 * 128];
    for (int i = threadIdx.x; i < 8 * Cin; i += 128) {
        int u = i / Cin, ci = i % Cin;
        ws[i] = w[((size_t)ci * Co + co0 + u) * 9 + k];
    }
    __syncthreads();
    const float4* xb = (const float4*)x + (size_t)b * Cin * HW4;
    float4 a0[8], a1[8];
    #pragma unroll
    for (int u = 0; u < 8; u++) { a0[u] = make_float4(0, 0, 0, 0); a1[u] = make_float4(0, 0, 0, 0); }
    for (int ci = 0; ci < Cin; ci++) {
        float4 x0 = xb[(size_t)ci * HW4 + p];
        float4 x1 = xb[(size_t)ci * HW4 + p + 128];
        if (na) {
            float aa = na[b * Cin + ci], cc = nc[b * Cin + ci];
            x0.x = fmaf(aa, x0.x, cc); x0.y = fmaf(aa, x0.y, cc);
            x0.z = fmaf(aa, x0.z, cc); x0.w = fmaf(aa, x0.w, cc);
            x1.x = fmaf(aa, x1.x, cc); x1.y = fmaf(aa, x1.y, cc);
            x1.z = fmaf(aa, x1.z, cc); x1.w = fmaf(aa, x1.w, cc);
        }
        #pragma unroll
        for (int u = 0; u < 8; u++) {
            float wv = ws[u * Cin + ci];
            a0[u].x = fmaf(wv, x0.x, a0[u].x); a0[u].y = fmaf(wv, x0.y, a0[u].y);
            a0[u].z = fmaf(wv, x0.z, a0[u].z); a0[u].w = fmaf(wv, x0.w, a0[u].w);
            a1[u].x = fmaf(wv, x1.x, a1[u].x); a1[u].y = fmaf(wv, x1.y, a1[u].y);
            a1[u].z = fmaf(wv, x1.z, a1[u].z); a1[u].w = fmaf(wv, x1.w, a1[u].w);
        }
    }
    float4* Mb = (float4*)M + (size_t)b * 9 * Co * HW4;
    #pragma unroll
    for (int u = 0; u < 8; u++) {
        Mb[(size_t)(kc0 + u) * HW4 + p] = a0[u];
        Mb[(size_t)(kc0 + u) * HW4 + p + 128] = a1[u];
    }
}

// ---------------- PAC combine ----------------
template<int CO_T>
__global__ void pac_combine(const float* __restrict__ M, const float* __restrict__ K,
                            const float* __restrict__ bias, float* __restrict__ out,
                            int Co, int Hs, int Ws) {
    int Ho = 2 * Hs, Wo = 2 * Ws;
    int px = blockIdx.x * 256 + threadIdx.x;
    int h = px / Wo, w = px % Wo;
    int co0 = blockIdx.y * CO_T;
    int b = blockIdx.z;

    float acc[CO_T];
    #pragma unroll
    for (int u = 0; u < CO_T; u++) acc[u] = bias[co0 + u];

    int nr, ry[2], rk[2];
    if (h & 1) {
        nr = 2; rk[0] = 0; ry[0] = (h - 1) >> 1; rk[1] = 2; ry[1] = (h + 1) >> 1;
        if (ry[1] >= Hs) nr = 1;
    } else { nr = 1; rk[0] = 1; ry[0] = h >> 1; }
    int ncn, cx[2], ck[2];
    if (w & 1) {
        ncn = 2; ck[0] = 0; cx[0] = (w - 1) >> 1; ck[1] = 2; cx[1] = (w + 1) >> 1;
        if (cx[1] >= Ws) ncn = 1;
    } else { ncn = 1; ck[0] = 1; cx[0] = w >> 1; }

    const float* Kb = K + (size_t)b * 9 * Ho * Wo + px;
    const float* Mb = M + (size_t)b * 9 * Co * Hs * Ws;
    int HsWs = Hs * Ws;
    for (int rr = 0; rr < nr; rr++)
        for (int cc = 0; cc < ncn; cc++) {
            int k = rk[rr] * 3 + ck[cc];
            float Kv = __ldg(Kb + (size_t)k * Ho * Wo);
            const float* Mp = Mb + ((size_t)k * Co + co0) * HsWs + ry[rr] * Ws + cx[cc];
            #pragma unroll
            for (int u = 0; u < CO_T; u++)
                acc[u] = fmaf(Kv, __ldg(Mp + (size_t)u * HsWs), acc[u]);
        }
    #pragma unroll
    for (int u = 0; u < CO_T; u++)
        out[(((size_t)b * Co + co0 + u) * Ho + h) * Wo + w] = acc[u];
}

// ---------------- driver ----------------
extern "C" void kernel_launch(void* const* d_in, const int* in_sizes, int n_in,
                              void* d_out, int out_size) {
    const float* x      = (const float*)d_in[0];
    const float* ef2    = (const float*)d_in[1];
    const float* ef1    = (const float*)d_in[2];
    const float* W_down = (const float*)d_in[3];
    const float* b_down = (const float*)d_in[4];
    const float* W_mid  = (const float*)d_in[5];
    const float* b_mid  = (const float*)d_in[6];
    const float* W_adj2 = (const float*)d_in[7];
    const float* b_adj2 = (const float*)d_in[8];
    const float* W_adj1 = (const float*)d_in[9];
    const float* b_adj1 = (const float*)d_in[10];
    const float* W16    = (const float*)d_in[11];
    const float* b16    = (const float*)d_in[12];
    const float* W20    = (const float*)d_in[13];
    const float* b20    = (const float*)d_in[14];
    const float* W24    = (const float*)d_in[15];
    const float* b24    = (const float*)d_in[16];
    float* out = (float*)d_out;

    float *t1, *part, *t2, *g2, *K1, *M1, *y1, *g1, *K2, *M2, *y2, *na, *nc;
    cudaGetSymbolAddress((void**)&t1, g_t1);
    cudaGetSymbolAddress((void**)&part, g_part);
    cudaGetSymbolAddress((void**)&t2, g_t2);
    cudaGetSymbolAddress((void**)&g2, g_g2);
    cudaGetSymbolAddress((void**)&K1, g_K1);
    cudaGetSymbolAddress((void**)&M1, g_M1);
    cudaGetSymbolAddress((void**)&y1, g_y1);
    cudaGetSymbolAddress((void**)&g1, g_g1);
    cudaGetSymbolAddress((void**)&K2, g_K2);
    cudaGetSymbolAddress((void**)&M2, g_M2);
    cudaGetSymbolAddress((void**)&y2, g_y2);
    cudaGetSymbolAddress((void**)&na, g_na);
    cudaGetSymbolAddress((void**)&nc, g_nc);

    dim3 cblk(16, 8);
    dim3 blk16(16, 16);

    // 1) inorm(x) coefficients (fused into stats)
    stats_coef<0><<<512, 256>>>(x, 64 * 64, na, nc);

    // 2) conv_down 256->128 @64x64, norm fused, Ci split G=2 -> partials, then reduce
    conv3x3_v2<16, 2, 2, false><<<dim3(8, 8, 4), cblk>>>(x, W_down, b_down, part,
                                                         256, 128, 64, 64, na, nc);
    reduce2_bias<<<4096, 256>>>(part, b_down, t1, 128, 64 * 64, 2 * 128 * 64 * 64);

    // 3) 1x1 + residual
    conv1x1_res4<<<dim3(8, 16, 2), 128>>>(t1, W_mid, b_mid, t2, 128, 1024);

    // 4) g2 = adjust_ef_lv2: 64->128 @128x128
    conv3x3_v2<16, 2, 1, true><<<dim3(32, 8, 2), cblk>>>(ef2, W_adj2, b_adj2, g2,
                                                         64, 128, 128, 128,
                                                         (const float*)0, (const float*)0);

    // 5) PAC kernel 1
    pac_kernel_K<<<dim3(64, 2), blk16>>>(g2, K1, 128, 128, 128);

    // 6) pacT1 = tap GEMM + combine: 128->64, 64x64 -> 128x128
    tap_gemm<<<dim3(4, 72, 2), 128>>>(t2, W16, M1, 128, 64, 1024,
                                      (const float*)0, (const float*)0);
    pac_combine<8><<<dim3(64, 8, 2), 256>>>(M1, K1, b16, y1, 64, 64, 64);

    // 7) dinorm coefs for y1 (affine fused into next tap_gemm)
    stats_coef<1><<<128, 256>>>(y1, 128 * 128, na, nc);

    // 8) g1 = adjust_ef_lv1: 32->64 @256x256
    conv3x3_v2<16, 2, 1, true><<<dim3(128, 4, 2), cblk>>>(ef1, W_adj1, b_adj1, g1,
                                                          32, 64, 256, 256,
                                                          (const float*)0, (const float*)0);

    // 9) PAC kernel 2
    pac_kernel_K<<<dim3(256, 2), blk16>>>(g1, K2, 64, 256, 256);

    // 10) pacT2 = tap GEMM (y1 affine fused) + combine: 64->32, 128x128 -> 256x256
    tap_gemm<<<dim3(16, 36, 2), 128>>>(y1, W20, M2, 64, 32, 4096, na, nc);
    pac_combine<8><<<dim3(256, 4, 2), 256>>>(M2, K2, b20, y2, 32, 128, 128);

    // 11) dinorm coefs for y2 (affine fused into final conv)
    stats_coef<1><<<64, 256>>>(y2, 256 * 256, na, nc);

    // 12) final conv 32->3 @256x256 (y2 affine fused)
    conv3x3_v2<3, 2, 1, true><<<dim3(128, 1, 2), cblk>>>(y2, W24, b24, out,
                                                         32, 3, 256, 256, na, nc);
}